// round 13
// baseline (speedup 1.0000x reference)
#include <cuda_runtime.h>
#include <stdint.h>

#define BATCH 16
#define H 128
#define W 128
#define HW (H*W)
#define CF 192
#define H2 64
#define W2 64
#define MAXRUN 8192

// per (batch, slot): [0..63] = source row indices, [64..127] = source col indices
__device__ int g_maps[BATCH][3][128];

__device__ __forceinline__ void ins3(unsigned long long &k0, unsigned long long &k1,
                                     unsigned long long &k2, unsigned long long x){
    if (x > k0){ k2 = k1; k1 = k0; k0 = x; }
    else if (x > k1){ k2 = k1; k1 = x; }
    else if (x > k2){ k2 = x; }
}

__global__ void __launch_bounds__(1024, 1) ccl_kernel(const float* __restrict__ prob){
    extern __shared__ int smem[];
    int*   L      = smem;                     // HW: pixel->runstart; runstart slots = UF parent
    int*   s_cnt  = smem + HW;                // run slots only (aliased as edge buf early)
    float* s_conf = (float*)(smem + 2*HW);    // run slots only (aliased as edge buf early)
    int*   E      = smem + HW;                // edge list, capacity 2*HW
    int*   R      = smem + 3*HW;              // run-start list, capacity MAXRUN

    __shared__ unsigned s_mask[HW/32];
    __shared__ unsigned long long s_r0[32], s_r1[32], s_r2[32];
    __shared__ int sK;
    __shared__ int s_slots[3];
    __shared__ int s_box[3][4];
    __shared__ int s_flag;
    __shared__ int s_ecnt, s_nrun;

    const int b    = blockIdx.x;
    const int tid  = threadIdx.x;
    const int lane = tid & 31;
    const float* pb = prob + (size_t)b * HW;

    // ---- pass 1: foreground bitmask via ballots ----
    #pragma unroll
    for (int i = tid; i < HW; i += 1024){
        float p = __ldg(&pb[i]);
        unsigned m = __ballot_sync(0xffffffffu, p > 0.5f);
        if (lane == 0) s_mask[i >> 5] = m;
    }
    if (tid == 0){ sK = 0; s_ecnt = 0; s_nrun = 0; }
    __syncthreads();

    #define SET(i) ((s_mask[(i) >> 5] >> ((i) & 31)) & 1u)

    // ---- pass 2: labels = run-start index; collect compact run list ----
    #pragma unroll
    for (int i = tid; i < HW; i += 1024){
        int v = -1;
        if (SET(i)){
            int c = i & (W - 1);
            int rowbase = i - c;
            const unsigned* rw = &s_mask[rowbase >> 5];
            int q = c >> 5, k = c & 31;
            unsigned lowm  = k ? ((1u << k) - 1u) : 0u;
            unsigned zeros = ~rw[q] & lowm;
            int start = 0;
            if (zeros) start = (q << 5) + (32 - __clz(zeros));
            else {
                for (int p = q - 1; p >= 0; p--){
                    unsigned z = ~rw[p];
                    if (z){ start = (p << 5) + (32 - __clz(z)); break; }
                }
            }
            v = rowbase + start;
        }
        L[i] = v;
        bool isr = (v == i);
        unsigned bal = __ballot_sync(0xffffffffu, isr);
        if (bal){
            int ldr = __ffs(bal) - 1;
            int base = 0;
            if (lane == ldr) base = atomicAdd(&s_nrun, __popc(bal));
            base = __shfl_sync(0xffffffffu, base, ldr);
            if (isr) R[base + __popc(bal & ((1u << lane) - 1u))] = i;
        }
    }
    __syncthreads();
    const int nrun = s_nrun;

    // ---- pass 3: deduped vertical edges as run-pair packs (warp-agg append) ----
    #pragma unroll
    for (int ii = 0; ii < 16; ii++){
        int i = W + ii * 1024 + tid;
        bool ok = (i < HW) && SET(i);
        int e0 = -1, e1 = -1;
        if (ok){
            int c = i & (W - 1);
            bool lft = (c > 0) && SET(i-1);
            if (SET(i-W)){
                if (!(lft && SET(i-W-1))) e0 = (L[i] << 14) | L[i-W];
            } else {
                if (c > 0     && SET(i-W-1) && !lft)      e0 = (L[i] << 14) | L[i-W-1];
                if (c < W-1   && SET(i-W+1) && !SET(i+1)) e1 = (L[i] << 14) | L[i-W+1];
            }
        }
        unsigned b0 = __ballot_sync(0xffffffffu, e0 >= 0);
        unsigned b1 = __ballot_sync(0xffffffffu, e1 >= 0);
        int tot = __popc(b0) + __popc(b1);
        int base = 0;
        if (lane == 0 && tot) base = atomicAdd(&s_ecnt, tot);
        base = __shfl_sync(0xffffffffu, base, 0);
        unsigned lt = (1u << lane) - 1u;
        if (e0 >= 0) E[base + __popc(b0 & lt)] = e0;
        if (e1 >= 0) E[base + __popc(b0) + __popc(b1 & lt)] = e1;
    }
    __syncthreads();
    const int ecnt   = s_ecnt;
    const int hiters = (ecnt + 1023) >> 10;

    // ---- SV rounds: hook edges (with in-place relabeling), halving flatten over runs ----
    for (int round = 0; round < 64; round++){
        if (tid == 0) s_flag = 0;
        __syncthreads();
        bool any = false;
        for (int ii = 0; ii < hiters; ii++){
            int e = ii * 1024 + tid;
            bool ok = e < ecnt;
            int hi = 0, lo = 0;
            if (ok){
                int pk = E[e];
                int a = pk >> 14, b2 = pk & 16383;
                int ra = L[a], rb = L[b2];
                int npk = (ra << 14) | rb;
                if (npk != pk) E[e] = npk;
                if (ra != rb){
                    hi = ra > rb ? ra : rb;
                    lo = ra > rb ? rb : ra;
                    any = true;
                } else ok = false;
            }
            unsigned act = __activemask();
            unsigned bal = __ballot_sync(act, ok);
            if (ok){
                unsigned grp = __match_any_sync(bal, hi) & bal;
                unsigned m   = __reduce_min_sync(grp, (unsigned)lo);
                if (lane == __ffs(grp) - 1) atomicMin(&L[hi], (int)m);
            }
        }
        if (any) s_flag = 1;
        __syncthreads();
        if (!s_flag) break;
        {   // path-halving flatten over runs: benign races, monotone decreasing
            volatile int* Lv = (volatile int*)L;
            for (int t = tid; t < nrun; t += 1024){
                int r = R[t];
                int x = r, p = Lv[x];
                for (;;){
                    int g = Lv[p];
                    if (g == p) break;
                    Lv[x] = g;
                    x = p; p = g;
                }
                if (Lv[r] != p) Lv[r] = p;
            }
        }
        __syncthreads();
    }

    // ---- zero stats at run slots ----
    for (int t = tid; t < nrun; t += 1024){
        int r = R[t];
        s_cnt[r] = 0; s_conf[r] = 0.f;
    }
    __syncthreads();

    // ---- conf & count per run: warp-segmented scan (runs contiguous in i) ----
    #pragma unroll 2
    for (int ii = 0; ii < 16; ii++){
        int i = ii * 1024 + tid;
        int rs = L[i];
        float s = (rs >= 0) ? __ldg(&pb[i]) : 0.f;
        int prev = __shfl_up_sync(0xffffffffu, rs, 1);
        bool head = (lane == 0) || (prev != rs);
        int seg = head ? lane : 0;
        #pragma unroll
        for (int off = 1; off < 32; off <<= 1){
            int v = __shfl_up_sync(0xffffffffu, seg, off);
            if (lane >= off && v > seg) seg = v;
        }
        #pragma unroll
        for (int off = 1; off < 32; off <<= 1){
            float v = __shfl_up_sync(0xffffffffu, s, off);
            if (lane - off >= seg) s += v;
        }
        int nxt = __shfl_down_sync(0xffffffffu, rs, 1);
        bool tail = (lane == 31) || (nxt != rs);
        if (tail && rs >= 0){
            atomicAdd(&s_conf[rs], s);              // spread addresses (per-run slots)
            atomicAdd(&s_cnt[rs],  lane - seg + 1);
        }
    }
    __syncthreads();

    // ---- push run stats to roots (warp-aggregated; few distinct roots/warp) ----
    for (int t0 = 0; t0 < nrun; t0 += 1024){
        int t = t0 + tid;
        bool ok = t < nrun;
        int root = 0, cnt = 0; float cf = 0.f;
        if (ok){
            int r = R[t];
            root = L[r];
            if (root != r){ cnt = s_cnt[r]; cf = s_conf[r]; }
            else ok = false;                         // root's own stats already in place
        }
        unsigned bal = __ballot_sync(0xffffffffu, ok);
        if (ok){
            unsigned grp = __match_any_sync(bal, root) & bal;
            int sumn = __reduce_add_sync(grp, cnt);
            float sumc = 0.f;
            unsigned m = grp;
            while (m){
                int l = __ffs(m) - 1;
                sumc += __shfl_sync(grp, cf, l);
                m &= m - 1;
            }
            if (lane == __ffs(grp) - 1){
                atomicAdd(&s_cnt[root], sumn);
                atomicAdd(&s_conf[root], sumc);
            }
        }
    }
    __syncthreads();

    // ---- top-3 by mean confidence + K (roots in run list) ----
    unsigned long long k0 = 0, k1 = 0, k2 = 0;
    int localK = 0;
    for (int t = tid; t < nrun; t += 1024){
        int r = R[t];
        if (L[r] == r){
            localK++;
            float mean = s_conf[r] / (float)s_cnt[r];   // in (0.5,1] => bit-monotone
            unsigned long long key =
                ((unsigned long long)__float_as_uint(mean) << 32) | (unsigned)(HW - 1 - r);
            ins3(k0, k1, k2, key);
        }
    }
    localK = __reduce_add_sync(0xffffffffu, localK);
    if (lane == 0) atomicAdd(&sK, localK);
    #pragma unroll
    for (int off = 16; off; off >>= 1){
        unsigned long long o0 = __shfl_down_sync(0xffffffffu, k0, off);
        unsigned long long o1 = __shfl_down_sync(0xffffffffu, k1, off);
        unsigned long long o2 = __shfl_down_sync(0xffffffffu, k2, off);
        ins3(k0, k1, k2, o0); ins3(k0, k1, k2, o1); ins3(k0, k1, k2, o2);
    }
    int wid = tid >> 5;
    if (lane == 0){ s_r0[wid] = k0; s_r1[wid] = k1; s_r2[wid] = k2; }
    __syncthreads();
    if (tid < 32){
        k0 = s_r0[tid]; k1 = s_r1[tid]; k2 = s_r2[tid];
        #pragma unroll
        for (int off = 16; off; off >>= 1){
            unsigned long long o0 = __shfl_down_sync(0xffffffffu, k0, off);
            unsigned long long o1 = __shfl_down_sync(0xffffffffu, k1, off);
            unsigned long long o2 = __shfl_down_sync(0xffffffffu, k2, off);
            ins3(k0, k1, k2, o0); ins3(k0, k1, k2, o1); ins3(k0, k1, k2, o2);
        }
        if (tid == 0){
            int K  = sK;
            int s0 = (HW - 1) - (int)(unsigned)(k0 & 0xffffffffull);
            int s1 = (HW - 1) - (int)(unsigned)(k1 & 0xffffffffull);
            int s2 = (HW - 1) - (int)(unsigned)(k2 & 0xffffffffull);
            int a0, a1, a2;
            if (K >= 3)      { a0 = s0; a1 = s1; a2 = s2; }
            else if (K == 2) { a0 = s0; a1 = s0; a2 = s1; }
            else             { a0 = s0; a1 = s0; a2 = s0; }
            s_slots[0] = a0; s_slots[1] = a1; s_slots[2] = a2;
            #pragma unroll
            for (int j = 0; j < 3; j++){
                s_box[j][0] = 0x7fffffff; s_box[j][1] = -1;
                s_box[j][2] = 0x7fffffff; s_box[j][3] = -1;
            }
        }
    }
    __syncthreads();

    // ---- bbox over runs (lazy run-end bitscan for matched runs only) ----
    if (sK > 0){
        for (int t0 = 0; t0 < nrun; t0 += 1024){
            int t = t0 + tid;
            bool ok = t < nrun;
            int root = -1, row = 0, c0 = 0, c1 = 0;
            if (ok){
                int r = R[t];
                root = L[r];
                row = r >> 7; c0 = r & (W - 1); c1 = c0;
                if (root == s_slots[0] || root == s_slots[1] || root == s_slots[2]){
                    const unsigned* rw = &s_mask[(r - c0) >> 5];
                    int q = c0 >> 5, k = c0 & 31;
                    unsigned him = (k == 31) ? 0u : ~((2u << k) - 1u);
                    unsigned z = ~rw[q] & him;
                    int end = W;
                    if (z) end = (q << 5) + (__ffs(z) - 1);
                    else {
                        for (int p = q + 1; p < 4; p++){
                            unsigned zz = ~rw[p];
                            if (zz){ end = (p << 5) + (__ffs(zz) - 1); break; }
                        }
                    }
                    c1 = end - 1;
                }
            }
            #pragma unroll
            for (int j = 0; j < 3; j++){
                bool mt = ok && (root == s_slots[j]);
                unsigned bal = __ballot_sync(0xffffffffu, mt);
                if (mt){
                    unsigned mnr = __reduce_min_sync(bal, (unsigned)row);
                    unsigned mxr = __reduce_max_sync(bal, (unsigned)row);
                    unsigned mnc = __reduce_min_sync(bal, (unsigned)c0);
                    unsigned mxc = __reduce_max_sync(bal, (unsigned)c1);
                    if (lane == (__ffs(bal) - 1)){
                        atomicMin(&s_box[j][0], (int)mnr);
                        atomicMax(&s_box[j][1], (int)mxr);
                        atomicMin(&s_box[j][2], (int)mnc);
                        atomicMax(&s_box[j][3], (int)mxc);
                    }
                }
            }
        }
    }
    __syncthreads();

    // ---- emit nearest-interp index maps (src = a + floor(dst*(b-a)/out)) ----
    if (tid < 384){
        int j = tid >> 7, q = tid & 127;
        int mr, Mr, mc, Mc;
        if (sK == 0){ mr = 0; Mr = H; mc = 0; Mc = W; }
        else {
            mr = s_box[j][0]; Mr = s_box[j][1] + 1;
            mc = s_box[j][2]; Mc = s_box[j][3] + 1;
        }
        int v;
        if (q < 64) v = mr + ((q * (Mr - mr)) >> 6);
        else        { int x = q - 64; v = mc + ((x * (Mc - mc)) >> 6); }
        g_maps[b][j][q] = v;
    }
}

// Empirically-fastest gather: one block per (b, slot, c) plane.
__global__ void __launch_bounds__(256) gather_kernel(const float* __restrict__ feat,
                                                     float* __restrict__ out){
    __shared__ int sm[128];
    int bid  = blockIdx.x;
    int c    = bid % CF;
    int rem  = bid / CF;
    int slot = rem % 3;
    int b    = rem / 3;

    if (threadIdx.x < 128) sm[threadIdx.x] = g_maps[b][slot][threadIdx.x];
    __syncthreads();
    const int* rmap = sm;
    const int* cmap = sm + 64;

    const float* src = feat + ((size_t)(b * CF + c)) * HW;
    float4* dst = (float4*)(out + ((size_t)b * (3 * CF) + (size_t)slot * CF + c) * (H2 * W2));

    #pragma unroll
    for (int i = threadIdx.x; i < (H2 * W2) / 4; i += 256){
        int y  = i >> 4;
        int x4 = (i & 15) << 2;
        const float* row = src + rmap[y] * W;
        float4 v;
        v.x = __ldg(&row[cmap[x4 + 0]]);
        v.y = __ldg(&row[cmap[x4 + 1]]);
        v.z = __ldg(&row[cmap[x4 + 2]]);
        v.w = __ldg(&row[cmap[x4 + 3]]);
        __stcs(&dst[i], v);
    }
}

extern "C" void kernel_launch(void* const* d_in, const int* in_sizes, int n_in,
                              void* d_out, int out_size){
    const float* prob = (const float*)d_in[0];
    const float* feat = (const float*)d_in[1];
    if (in_sizes[0] != BATCH * HW){
        const float* t = prob; prob = feat; feat = t;
    }
    const int ccl_smem = (3 * HW + MAXRUN) * 4;            // 224KB
    cudaFuncSetAttribute(ccl_kernel, cudaFuncAttributeMaxDynamicSharedMemorySize, ccl_smem);

    ccl_kernel<<<BATCH, 1024, ccl_smem>>>(prob);
    gather_kernel<<<BATCH * 3 * CF, 256>>>(feat, (float*)d_out);
}

// round 14
// speedup vs baseline: 1.8423x; 1.8423x over previous
#include <cuda_runtime.h>
#include <stdint.h>

#define BATCH 16
#define H 128
#define W 128
#define HW (H*W)
#define CF 192
#define H2 64
#define W2 64
#define MAXRUN 8192

// per (batch, slot): [0..63] = source row indices, [64..127] = source col indices
__device__ int g_maps[BATCH][3][128];

__device__ __forceinline__ void ins3(unsigned long long &k0, unsigned long long &k1,
                                     unsigned long long &k2, unsigned long long x){
    if (x > k0){ k2 = k1; k1 = k0; k0 = x; }
    else if (x > k1){ k2 = k1; k1 = x; }
    else if (x > k2){ k2 = x; }
}

__global__ void __launch_bounds__(1024, 1) ccl_kernel(const float* __restrict__ prob){
    extern __shared__ int smem[];
    int*   L      = smem;                     // HW: pixel->runstart; runstart slots = UF parent
    int*   s_cnt  = smem + HW;                // HW ints   (aliased as edge buf early)
    float* s_conf = (float*)(smem + 2*HW);    // HW floats (aliased as edge buf early)
    int*   E      = smem + HW;                // edge list, capacity 2*HW
    int*   R      = smem + 3*HW;              // run-start list, capacity MAXRUN

    __shared__ unsigned s_mask[HW/32];
    __shared__ unsigned long long s_r0[32], s_r1[32], s_r2[32];
    __shared__ int sK;
    __shared__ int s_slots[3];
    __shared__ int s_box[3][4];
    __shared__ int s_flag;
    __shared__ int s_ecnt, s_nrun;

    const int b    = blockIdx.x;
    const int tid  = threadIdx.x;
    const int lane = tid & 31;
    const float* pb = prob + (size_t)b * HW;

    // ---- pass 1: foreground bitmask via ballots ----
    #pragma unroll
    for (int i = tid; i < HW; i += 1024){
        float p = __ldg(&pb[i]);
        unsigned m = __ballot_sync(0xffffffffu, p > 0.5f);
        if (lane == 0) s_mask[i >> 5] = m;
    }
    if (tid == 0){ sK = 0; s_ecnt = 0; s_nrun = 0; }
    __syncthreads();

    #define SET(i) ((s_mask[(i) >> 5] >> ((i) & 31)) & 1u)

    // ---- pass 2: labels = run-start index; collect compact run list ----
    #pragma unroll
    for (int i = tid; i < HW; i += 1024){
        int v = -1;
        if (SET(i)){
            int c = i & (W - 1);
            int rowbase = i - c;
            const unsigned* rw = &s_mask[rowbase >> 5];
            int q = c >> 5, k = c & 31;
            unsigned lowm  = k ? ((1u << k) - 1u) : 0u;
            unsigned zeros = ~rw[q] & lowm;
            int start = 0;
            if (zeros) start = (q << 5) + (32 - __clz(zeros));
            else {
                for (int p = q - 1; p >= 0; p--){
                    unsigned z = ~rw[p];
                    if (z){ start = (p << 5) + (32 - __clz(z)); break; }
                }
            }
            v = rowbase + start;
        }
        L[i] = v;
        bool isr = (v == i);
        unsigned bal = __ballot_sync(0xffffffffu, isr);
        if (bal){
            int ldr = __ffs(bal) - 1;
            int base = 0;
            if (lane == ldr) base = atomicAdd(&s_nrun, __popc(bal));
            base = __shfl_sync(0xffffffffu, base, ldr);
            if (isr) R[base + __popc(bal & ((1u << lane) - 1u))] = i;
        }
    }
    __syncthreads();
    const int nrun = s_nrun;

    // ---- pass 3: deduped vertical edges as run-pair packs (warp-agg append) ----
    #pragma unroll
    for (int ii = 0; ii < 16; ii++){
        int i = W + ii * 1024 + tid;
        bool ok = (i < HW) && SET(i);
        int e0 = -1, e1 = -1;
        if (ok){
            int c = i & (W - 1);
            bool lft = (c > 0) && SET(i-1);
            if (SET(i-W)){
                if (!(lft && SET(i-W-1))) e0 = (L[i] << 14) | L[i-W];
            } else {
                if (c > 0     && SET(i-W-1) && !lft)      e0 = (L[i] << 14) | L[i-W-1];
                if (c < W-1   && SET(i-W+1) && !SET(i+1)) e1 = (L[i] << 14) | L[i-W+1];
            }
        }
        unsigned b0 = __ballot_sync(0xffffffffu, e0 >= 0);
        unsigned b1 = __ballot_sync(0xffffffffu, e1 >= 0);
        int tot = __popc(b0) + __popc(b1);
        int base = 0;
        if (lane == 0 && tot) base = atomicAdd(&s_ecnt, tot);
        base = __shfl_sync(0xffffffffu, base, 0);
        unsigned lt = (1u << lane) - 1u;
        if (e0 >= 0) E[base + __popc(b0 & lt)] = e0;
        if (e1 >= 0) E[base + __popc(b0) + __popc(b1 & lt)] = e1;
    }
    __syncthreads();
    const int ecnt   = s_ecnt;
    const int hiters = (ecnt + 1023) >> 10;

    // ---- SV rounds: hook edges (with in-place relabeling), halving flatten ----
    for (int round = 0; round < 64; round++){
        if (tid == 0) s_flag = 0;
        __syncthreads();
        bool any = false;
        for (int ii = 0; ii < hiters; ii++){
            int e = ii * 1024 + tid;
            bool ok = e < ecnt;
            int hi = 0, lo = 0;
            if (ok){
                int pk = E[e];
                int a = pk >> 14, b2 = pk & 16383;
                int ra = L[a], rb = L[b2];
                int npk = (ra << 14) | rb;
                if (npk != pk) E[e] = npk;
                if (ra != rb){
                    hi = ra > rb ? ra : rb;
                    lo = ra > rb ? rb : ra;
                    any = true;
                } else ok = false;
            }
            unsigned act = __activemask();
            unsigned bal = __ballot_sync(act, ok);
            if (ok){
                unsigned grp = __match_any_sync(bal, hi) & bal;
                unsigned m   = __reduce_min_sync(grp, (unsigned)lo);
                if (lane == __ffs(grp) - 1) atomicMin(&L[hi], (int)m);
            }
        }
        if (any) s_flag = 1;
        __syncthreads();
        if (!s_flag) break;
        {   // path-halving flatten over runs: benign races, monotone decreasing
            volatile int* Lv = (volatile int*)L;
            for (int t = tid; t < nrun; t += 1024){
                int r = R[t];
                int x = r, p = Lv[x];
                for (;;){
                    int g = Lv[p];
                    if (g == p) break;
                    Lv[x] = g;
                    x = p; p = g;
                }
                if (Lv[r] != p) Lv[r] = p;
            }
        }
        __syncthreads();
    }

    // ---- propagate root to every pixel ----
    for (int i = tid; i < HW; i += 1024){
        int p = L[i];
        if (p >= 0) L[i] = L[p];
    }
    __syncthreads();

    // ---- zero stats at run-start slots only (edges dead now) ----
    for (int t = tid; t < nrun; t += 1024){
        int r = R[t];
        s_cnt[r] = 0; s_conf[r] = 0.f;
    }
    __syncthreads();

    // ---- per-component count & conf-sum (warp-aggregated shared atomics;
    //      background lanes skip the discarded group-sum) ----
    for (int i = tid; i < HW; i += 1024){
        int root = L[i];
        unsigned grp = __match_any_sync(0xffffffffu, root);
        if (root >= 0){
            float p = __ldg(&pb[i]);
            float s = 0.f;
            unsigned m = grp;
            while (m){
                int l = __ffs(m) - 1;
                s += __shfl_sync(grp, p, l);
                m &= m - 1;
            }
            if (lane == (__ffs(grp) - 1)){
                atomicAdd(&s_cnt[root],  __popc(grp));
                atomicAdd(&s_conf[root], s);
            }
        }
    }
    __syncthreads();

    // ---- top-3 by mean confidence + K (scan runs, not pixels) ----
    unsigned long long k0 = 0, k1 = 0, k2 = 0;
    int localK = 0;
    for (int t = tid; t < nrun; t += 1024){
        int r = R[t];
        int cnt = s_cnt[r];
        if (cnt > 0){                               // r is a root
            localK++;
            float mean = s_conf[r] / (float)cnt;    // in (0.5,1] => bit-monotone
            unsigned long long key =
                ((unsigned long long)__float_as_uint(mean) << 32) | (unsigned)(HW - 1 - r);
            ins3(k0, k1, k2, key);
        }
    }
    localK = __reduce_add_sync(0xffffffffu, localK);     // one atomic per warp
    if (lane == 0) atomicAdd(&sK, localK);
    #pragma unroll
    for (int off = 16; off; off >>= 1){
        unsigned long long o0 = __shfl_down_sync(0xffffffffu, k0, off);
        unsigned long long o1 = __shfl_down_sync(0xffffffffu, k1, off);
        unsigned long long o2 = __shfl_down_sync(0xffffffffu, k2, off);
        ins3(k0, k1, k2, o0); ins3(k0, k1, k2, o1); ins3(k0, k1, k2, o2);
    }
    int wid = tid >> 5;
    if (lane == 0){ s_r0[wid] = k0; s_r1[wid] = k1; s_r2[wid] = k2; }
    __syncthreads();
    if (tid < 32){
        k0 = s_r0[tid]; k1 = s_r1[tid]; k2 = s_r2[tid];
        #pragma unroll
        for (int off = 16; off; off >>= 1){
            unsigned long long o0 = __shfl_down_sync(0xffffffffu, k0, off);
            unsigned long long o1 = __shfl_down_sync(0xffffffffu, k1, off);
            unsigned long long o2 = __shfl_down_sync(0xffffffffu, k2, off);
            ins3(k0, k1, k2, o0); ins3(k0, k1, k2, o1); ins3(k0, k1, k2, o2);
        }
        if (tid == 0){
            int K  = sK;
            int s0 = (HW - 1) - (int)(unsigned)(k0 & 0xffffffffull);
            int s1 = (HW - 1) - (int)(unsigned)(k1 & 0xffffffffull);
            int s2 = (HW - 1) - (int)(unsigned)(k2 & 0xffffffffull);
            int a0, a1, a2;
            if (K >= 3)      { a0 = s0; a1 = s1; a2 = s2; }
            else if (K == 2) { a0 = s0; a1 = s0; a2 = s1; }
            else             { a0 = s0; a1 = s0; a2 = s0; }
            s_slots[0] = a0; s_slots[1] = a1; s_slots[2] = a2;
            #pragma unroll
            for (int j = 0; j < 3; j++){
                s_box[j][0] = 0x7fffffff; s_box[j][1] = -1;
                s_box[j][2] = 0x7fffffff; s_box[j][3] = -1;
            }
        }
    }
    __syncthreads();

    // ---- bbox scan for the <=3 selected components ----
    if (sK > 0){
        for (int i = tid; i < HW; i += 1024){
            int root = L[i];
            int r = i >> 7, c = i & (W - 1);
            #pragma unroll
            for (int j = 0; j < 3; j++){
                bool mt = (root >= 0) && (root == s_slots[j]);
                unsigned bal = __ballot_sync(0xffffffffu, mt);
                if (mt){
                    unsigned mnr = __reduce_min_sync(bal, (unsigned)r);
                    unsigned mxr = __reduce_max_sync(bal, (unsigned)r);
                    unsigned mnc = __reduce_min_sync(bal, (unsigned)c);
                    unsigned mxc = __reduce_max_sync(bal, (unsigned)c);
                    if (lane == (__ffs(bal) - 1)){
                        atomicMin(&s_box[j][0], (int)mnr);
                        atomicMax(&s_box[j][1], (int)mxr);
                        atomicMin(&s_box[j][2], (int)mnc);
                        atomicMax(&s_box[j][3], (int)mxc);
                    }
                }
            }
        }
    }
    __syncthreads();

    // ---- emit nearest-interp index maps (src = a + floor(dst*(b-a)/out)) ----
    if (tid < 384){
        int j = tid >> 7, q = tid & 127;
        int mr, Mr, mc, Mc;
        if (sK == 0){ mr = 0; Mr = H; mc = 0; Mc = W; }
        else {
            mr = s_box[j][0]; Mr = s_box[j][1] + 1;
            mc = s_box[j][2]; Mc = s_box[j][3] + 1;
        }
        int v;
        if (q < 64) v = mr + ((q * (Mr - mr)) >> 6);
        else        { int x = q - 64; v = mc + ((x * (Mc - mc)) >> 6); }
        g_maps[b][j][q] = v;
    }
}

// Empirically-fastest gather: one block per (b, slot, c) plane.
__global__ void __launch_bounds__(256) gather_kernel(const float* __restrict__ feat,
                                                     float* __restrict__ out){
    __shared__ int sm[128];
    int bid  = blockIdx.x;
    int c    = bid % CF;
    int rem  = bid / CF;
    int slot = rem % 3;
    int b    = rem / 3;

    if (threadIdx.x < 128) sm[threadIdx.x] = g_maps[b][slot][threadIdx.x];
    __syncthreads();
    const int* rmap = sm;
    const int* cmap = sm + 64;

    const float* src = feat + ((size_t)(b * CF + c)) * HW;
    float4* dst = (float4*)(out + ((size_t)b * (3 * CF) + (size_t)slot * CF + c) * (H2 * W2));

    #pragma unroll
    for (int i = threadIdx.x; i < (H2 * W2) / 4; i += 256){
        int y  = i >> 4;
        int x4 = (i & 15) << 2;
        const float* row = src + rmap[y] * W;
        float4 v;
        v.x = __ldg(&row[cmap[x4 + 0]]);
        v.y = __ldg(&row[cmap[x4 + 1]]);
        v.z = __ldg(&row[cmap[x4 + 2]]);
        v.w = __ldg(&row[cmap[x4 + 3]]);
        __stcs(&dst[i], v);
    }
}

extern "C" void kernel_launch(void* const* d_in, const int* in_sizes, int n_in,
                              void* d_out, int out_size){
    const float* prob = (const float*)d_in[0];
    const float* feat = (const float*)d_in[1];
    if (in_sizes[0] != BATCH * HW){
        const float* t = prob; prob = feat; feat = t;
    }
    const int ccl_smem = (3 * HW + MAXRUN) * 4;            // 224KB
    cudaFuncSetAttribute(ccl_kernel, cudaFuncAttributeMaxDynamicSharedMemorySize, ccl_smem);

    ccl_kernel<<<BATCH, 1024, ccl_smem>>>(prob);
    gather_kernel<<<BATCH * 3 * CF, 256>>>(feat, (float*)d_out);
}

// round 15
// speedup vs baseline: 1.8501x; 1.0042x over previous
#include <cuda_runtime.h>
#include <stdint.h>

#define BATCH 16
#define H 128
#define W 128
#define HW (H*W)
#define CF 192
#define H2 64
#define W2 64
#define MAXRUN 8192

// per (batch, slot): [0..63] = source row indices, [64..127] = source col indices
__device__ int g_maps[BATCH][3][128];

__device__ __forceinline__ void ins3(unsigned long long &k0, unsigned long long &k1,
                                     unsigned long long &k2, unsigned long long x){
    if (x > k0){ k2 = k1; k1 = k0; k0 = x; }
    else if (x > k1){ k2 = k1; k1 = x; }
    else if (x > k2){ k2 = x; }
}

__global__ void __launch_bounds__(1024, 1) ccl_kernel(const float* __restrict__ prob){
    extern __shared__ int smem[];
    int* L = smem;                                        // HW: pixel->runstart; run slots = UF parent
    unsigned long long* s_acc = (unsigned long long*)(smem + HW); // HW ull: (cnt<<40)|sum_fixed
    int* E = smem + HW;                                   // edge list (aliases s_acc; dead before stats)
    int* R = smem + 3*HW;                                 // run-start list, capacity MAXRUN

    __shared__ unsigned s_mask[HW/32];
    __shared__ unsigned long long s_r0[32], s_r1[32], s_r2[32];
    __shared__ int sK;
    __shared__ int s_slots[3];
    __shared__ int s_box[3][4];
    __shared__ int s_flag;
    __shared__ int s_ecnt, s_nrun;

    const int b    = blockIdx.x;
    const int tid  = threadIdx.x;
    const int lane = tid & 31;
    const float* pb = prob + (size_t)b * HW;

    // ---- pass 1: foreground bitmask via ballots ----
    #pragma unroll
    for (int i = tid; i < HW; i += 1024){
        float p = __ldg(&pb[i]);
        unsigned m = __ballot_sync(0xffffffffu, p > 0.5f);
        if (lane == 0) s_mask[i >> 5] = m;
    }
    if (tid == 0){ sK = 0; s_ecnt = 0; s_nrun = 0; }
    __syncthreads();

    #define SET(i) ((s_mask[(i) >> 5] >> ((i) & 31)) & 1u)

    // ---- pass 2: labels = run-start index; collect compact run list ----
    #pragma unroll
    for (int i = tid; i < HW; i += 1024){
        int v = -1;
        if (SET(i)){
            int c = i & (W - 1);
            int rowbase = i - c;
            const unsigned* rw = &s_mask[rowbase >> 5];
            int q = c >> 5, k = c & 31;
            unsigned lowm  = k ? ((1u << k) - 1u) : 0u;
            unsigned zeros = ~rw[q] & lowm;
            int start = 0;
            if (zeros) start = (q << 5) + (32 - __clz(zeros));
            else {
                for (int p = q - 1; p >= 0; p--){
                    unsigned z = ~rw[p];
                    if (z){ start = (p << 5) + (32 - __clz(z)); break; }
                }
            }
            v = rowbase + start;
        }
        L[i] = v;
        bool isr = (v == i);
        unsigned bal = __ballot_sync(0xffffffffu, isr);
        if (bal){
            int ldr = __ffs(bal) - 1;
            int base = 0;
            if (lane == ldr) base = atomicAdd(&s_nrun, __popc(bal));
            base = __shfl_sync(0xffffffffu, base, ldr);
            if (isr) R[base + __popc(bal & ((1u << lane) - 1u))] = i;
        }
    }
    __syncthreads();
    const int nrun = s_nrun;

    // ---- pass 3: deduped vertical edges as run-pair packs (warp-agg append) ----
    #pragma unroll
    for (int ii = 0; ii < 16; ii++){
        int i = W + ii * 1024 + tid;
        bool ok = (i < HW) && SET(i);
        int e0 = -1, e1 = -1;
        if (ok){
            int c = i & (W - 1);
            bool lft = (c > 0) && SET(i-1);
            if (SET(i-W)){
                if (!(lft && SET(i-W-1))) e0 = (L[i] << 14) | L[i-W];
            } else {
                if (c > 0     && SET(i-W-1) && !lft)      e0 = (L[i] << 14) | L[i-W-1];
                if (c < W-1   && SET(i-W+1) && !SET(i+1)) e1 = (L[i] << 14) | L[i-W+1];
            }
        }
        unsigned b0 = __ballot_sync(0xffffffffu, e0 >= 0);
        unsigned b1 = __ballot_sync(0xffffffffu, e1 >= 0);
        int tot = __popc(b0) + __popc(b1);
        int base = 0;
        if (lane == 0 && tot) base = atomicAdd(&s_ecnt, tot);
        base = __shfl_sync(0xffffffffu, base, 0);
        unsigned lt = (1u << lane) - 1u;
        if (e0 >= 0) E[base + __popc(b0 & lt)] = e0;
        if (e1 >= 0) E[base + __popc(b0) + __popc(b1 & lt)] = e1;
    }
    __syncthreads();
    const int ecnt   = s_ecnt;
    const int hiters = (ecnt + 1023) >> 10;

    // ---- SV rounds: hook edges (with in-place relabeling), halving flatten ----
    for (int round = 0; round < 64; round++){
        if (tid == 0) s_flag = 0;
        __syncthreads();
        bool any = false;
        for (int ii = 0; ii < hiters; ii++){
            int e = ii * 1024 + tid;
            bool ok = e < ecnt;
            int hi = 0, lo = 0;
            if (ok){
                int pk = E[e];
                int a = pk >> 14, b2 = pk & 16383;
                int ra = L[a], rb = L[b2];
                int npk = (ra << 14) | rb;
                if (npk != pk) E[e] = npk;
                if (ra != rb){
                    hi = ra > rb ? ra : rb;
                    lo = ra > rb ? rb : ra;
                    any = true;
                } else ok = false;
            }
            unsigned act = __activemask();
            unsigned bal = __ballot_sync(act, ok);
            if (ok){
                unsigned grp = __match_any_sync(bal, hi) & bal;
                unsigned m   = __reduce_min_sync(grp, (unsigned)lo);
                if (lane == __ffs(grp) - 1) atomicMin(&L[hi], (int)m);
            }
        }
        if (any) s_flag = 1;
        __syncthreads();
        if (!s_flag) break;
        {   // path-halving flatten over runs: benign races, monotone decreasing
            volatile int* Lv = (volatile int*)L;
            for (int t = tid; t < nrun; t += 1024){
                int r = R[t];
                int x = r, p = Lv[x];
                for (;;){
                    int g = Lv[p];
                    if (g == p) break;
                    Lv[x] = g;
                    x = p; p = g;
                }
                if (Lv[r] != p) Lv[r] = p;
            }
        }
        __syncthreads();
    }

    // ---- propagate root to every pixel ----
    for (int i = tid; i < HW; i += 1024){
        int p = L[i];
        if (p >= 0) L[i] = L[p];
    }
    __syncthreads();

    // ---- zero stats at run-start slots only (edges dead now) ----
    for (int t = tid; t < nrun; t += 1024){
        s_acc[R[t]] = 0ull;
    }
    __syncthreads();

    // ---- per-component count & conf-sum: exact fixed-point REDUX + one
    //      fused 64-bit atomic per group leader.  p in (0.5,1) is exactly
    //      k*2^-24, so p*2^24 converts with ZERO rounding error. ----
    for (int i = tid; i < HW; i += 1024){
        int root = L[i];
        unsigned grp = __match_any_sync(0xffffffffu, root);
        if (root >= 0){
            unsigned fx = __float2uint_rn(__ldg(&pb[i]) * 16777216.0f);  // exact
            unsigned s  = __reduce_add_sync(grp, fx);                    // <= 32*2^24 < 2^30
            if (lane == (__ffs(grp) - 1))
                atomicAdd(&s_acc[root],
                          ((unsigned long long)__popc(grp) << 40) | (unsigned long long)s);
        }
    }
    __syncthreads();

    // ---- top-3 by mean confidence + K (scan runs, not pixels) ----
    unsigned long long k0 = 0, k1 = 0, k2 = 0;
    int localK = 0;
    for (int t = tid; t < nrun; t += 1024){
        int r = R[t];
        unsigned long long v = s_acc[r];
        if (v != 0ull){                              // r is a root with pixels
            localK++;
            unsigned cnt = (unsigned)(v >> 40);
            unsigned long long sum = v & ((1ull << 40) - 1ull);
            // exact-rational mean; double divide, then to float (bit-monotone > 0).
            float mean = (float)((double)sum / ((double)cnt * 16777216.0));
            unsigned long long key =
                ((unsigned long long)__float_as_uint(mean) << 32) | (unsigned)(HW - 1 - r);
            ins3(k0, k1, k2, key);
        }
    }
    localK = __reduce_add_sync(0xffffffffu, localK);     // one atomic per warp
    if (lane == 0) atomicAdd(&sK, localK);
    #pragma unroll
    for (int off = 16; off; off >>= 1){
        unsigned long long o0 = __shfl_down_sync(0xffffffffu, k0, off);
        unsigned long long o1 = __shfl_down_sync(0xffffffffu, k1, off);
        unsigned long long o2 = __shfl_down_sync(0xffffffffu, k2, off);
        ins3(k0, k1, k2, o0); ins3(k0, k1, k2, o1); ins3(k0, k1, k2, o2);
    }
    int wid = tid >> 5;
    if (lane == 0){ s_r0[wid] = k0; s_r1[wid] = k1; s_r2[wid] = k2; }
    __syncthreads();
    if (tid < 32){
        k0 = s_r0[tid]; k1 = s_r1[tid]; k2 = s_r2[tid];
        #pragma unroll
        for (int off = 16; off; off >>= 1){
            unsigned long long o0 = __shfl_down_sync(0xffffffffu, k0, off);
            unsigned long long o1 = __shfl_down_sync(0xffffffffu, k1, off);
            unsigned long long o2 = __shfl_down_sync(0xffffffffu, k2, off);
            ins3(k0, k1, k2, o0); ins3(k0, k1, k2, o1); ins3(k0, k1, k2, o2);
        }
        if (tid == 0){
            int K  = sK;
            int s0 = (HW - 1) - (int)(unsigned)(k0 & 0xffffffffull);
            int s1 = (HW - 1) - (int)(unsigned)(k1 & 0xffffffffull);
            int s2 = (HW - 1) - (int)(unsigned)(k2 & 0xffffffffull);
            int a0, a1, a2;
            if (K >= 3)      { a0 = s0; a1 = s1; a2 = s2; }
            else if (K == 2) { a0 = s0; a1 = s0; a2 = s1; }
            else             { a0 = s0; a1 = s0; a2 = s0; }
            s_slots[0] = a0; s_slots[1] = a1; s_slots[2] = a2;
            #pragma unroll
            for (int j = 0; j < 3; j++){
                s_box[j][0] = 0x7fffffff; s_box[j][1] = -1;
                s_box[j][2] = 0x7fffffff; s_box[j][3] = -1;
            }
        }
    }
    __syncthreads();

    // ---- bbox scan for the <=3 selected components ----
    if (sK > 0){
        for (int i = tid; i < HW; i += 1024){
            int root = L[i];
            int r = i >> 7, c = i & (W - 1);
            #pragma unroll
            for (int j = 0; j < 3; j++){
                bool mt = (root >= 0) && (root == s_slots[j]);
                unsigned bal = __ballot_sync(0xffffffffu, mt);
                if (mt){
                    unsigned mnr = __reduce_min_sync(bal, (unsigned)r);
                    unsigned mxr = __reduce_max_sync(bal, (unsigned)r);
                    unsigned mnc = __reduce_min_sync(bal, (unsigned)c);
                    unsigned mxc = __reduce_max_sync(bal, (unsigned)c);
                    if (lane == (__ffs(bal) - 1)){
                        atomicMin(&s_box[j][0], (int)mnr);
                        atomicMax(&s_box[j][1], (int)mxr);
                        atomicMin(&s_box[j][2], (int)mnc);
                        atomicMax(&s_box[j][3], (int)mxc);
                    }
                }
            }
        }
    }
    __syncthreads();

    // ---- emit nearest-interp index maps (src = a + floor(dst*(b-a)/out)) ----
    if (tid < 384){
        int j = tid >> 7, q = tid & 127;
        int mr, Mr, mc, Mc;
        if (sK == 0){ mr = 0; Mr = H; mc = 0; Mc = W; }
        else {
            mr = s_box[j][0]; Mr = s_box[j][1] + 1;
            mc = s_box[j][2]; Mc = s_box[j][3] + 1;
        }
        int v;
        if (q < 64) v = mr + ((q * (Mr - mr)) >> 6);
        else        { int x = q - 64; v = mc + ((x * (Mc - mc)) >> 6); }
        g_maps[b][j][q] = v;
    }
}

// Empirically-fastest gather: one block per (b, slot, c) plane.
__global__ void __launch_bounds__(256) gather_kernel(const float* __restrict__ feat,
                                                     float* __restrict__ out){
    __shared__ int sm[128];
    int bid  = blockIdx.x;
    int c    = bid % CF;
    int rem  = bid / CF;
    int slot = rem % 3;
    int b    = rem / 3;

    if (threadIdx.x < 128) sm[threadIdx.x] = g_maps[b][slot][threadIdx.x];
    __syncthreads();
    const int* rmap = sm;
    const int* cmap = sm + 64;

    const float* src = feat + ((size_t)(b * CF + c)) * HW;
    float4* dst = (float4*)(out + ((size_t)b * (3 * CF) + (size_t)slot * CF + c) * (H2 * W2));

    #pragma unroll
    for (int i = threadIdx.x; i < (H2 * W2) / 4; i += 256){
        int y  = i >> 4;
        int x4 = (i & 15) << 2;
        const float* row = src + rmap[y] * W;
        float4 v;
        v.x = __ldg(&row[cmap[x4 + 0]]);
        v.y = __ldg(&row[cmap[x4 + 1]]);
        v.z = __ldg(&row[cmap[x4 + 2]]);
        v.w = __ldg(&row[cmap[x4 + 3]]);
        __stcs(&dst[i], v);
    }
}

extern "C" void kernel_launch(void* const* d_in, const int* in_sizes, int n_in,
                              void* d_out, int out_size){
    const float* prob = (const float*)d_in[0];
    const float* feat = (const float*)d_in[1];
    if (in_sizes[0] != BATCH * HW){
        const float* t = prob; prob = feat; feat = t;
    }
    const int ccl_smem = (3 * HW + MAXRUN) * 4;            // 224KB (L + acc/E + R)
    cudaFuncSetAttribute(ccl_kernel, cudaFuncAttributeMaxDynamicSharedMemorySize, ccl_smem);

    ccl_kernel<<<BATCH, 1024, ccl_smem>>>(prob);
    gather_kernel<<<BATCH * 3 * CF, 256>>>(feat, (float*)d_out);
}

// round 17
// speedup vs baseline: 1.8776x; 1.0149x over previous
#include <cuda_runtime.h>
#include <stdint.h>

#define BATCH 16
#define H 128
#define W 128
#define HW (H*W)
#define CF 192
#define H2 64
#define W2 64
#define MAXRUN 8192

// per (batch, slot): [0..63] = source row indices, [64..127] = source col indices
__device__ int g_maps[BATCH][3][128];

__device__ __forceinline__ void ins3(unsigned long long &k0, unsigned long long &k1,
                                     unsigned long long &k2, unsigned long long x){
    if (x > k0){ k2 = k1; k1 = k0; k0 = x; }
    else if (x > k1){ k2 = k1; k1 = x; }
    else if (x > k2){ k2 = x; }
}

__global__ void __launch_bounds__(1024, 1) ccl_kernel(const float* __restrict__ prob){
    extern __shared__ int smem[];
    int* L = smem;                                        // HW: pixel->runstart; run slots = UF parent
    unsigned long long* s_acc = (unsigned long long*)(smem + HW); // HW ull: (cnt<<40)|sum_fixed
    int* E = smem + HW;                                   // edge segments (alias s_acc; dead pre-stats)
    int* R = smem + 3*HW;                                 // run segments: 256 slots per warp

    __shared__ unsigned s_mask[HW/32];                    // 2048 B
    __shared__ unsigned long long s_r0[32], s_r1[32], s_r2[32];  // 768 B
    __shared__ int s_wcnt[32];                            // 128 B: runs | edges<<16
    __shared__ int sK;
    __shared__ int s_slots[3];
    __shared__ int s_box[3][4];
    __shared__ int s_flag;                                // statics total ~3012 B (fits w/ 224KB dyn)

    const int b    = blockIdx.x;
    const int tid  = threadIdx.x;
    const int lane = tid & 31;
    const int w    = tid >> 5;
    const float* pb = prob + (size_t)b * HW;

    // ---- pass 1: foreground bitmask via ballots ----
    #pragma unroll
    for (int i = tid; i < HW; i += 1024){
        float p = __ldg(&pb[i]);
        unsigned m = __ballot_sync(0xffffffffu, p > 0.5f);
        if (lane == 0) s_mask[i >> 5] = m;
    }
    if (tid == 0) sK = 0;
    __syncthreads();

    #define SET(i) ((s_mask[(i) >> 5] >> ((i) & 31)) & 1u)

    // ---- pass 2: labels = run-start index; runs into PER-WARP segments ----
    int runcnt;
    {
        int* Rw = R + (w << 8);
        int wcnt = 0;
        const unsigned lt = (1u << lane) - 1u;
        #pragma unroll
        for (int ii = 0; ii < 16; ii++){
            int i = ii * 1024 + tid;
            int v = -1;
            if (SET(i)){
                int c = i & (W - 1);
                int rowbase = i - c;
                const unsigned* rw = &s_mask[rowbase >> 5];
                int q = c >> 5, k = c & 31;
                unsigned lowm  = k ? ((1u << k) - 1u) : 0u;
                unsigned zeros = ~rw[q] & lowm;
                int start = 0;
                if (zeros) start = (q << 5) + (32 - __clz(zeros));
                else {
                    for (int p = q - 1; p >= 0; p--){
                        unsigned z = ~rw[p];
                        if (z){ start = (p << 5) + (32 - __clz(z)); break; }
                    }
                }
                v = rowbase + start;
            }
            L[i] = v;
            bool isr = (v == i);
            unsigned bal = __ballot_sync(0xffffffffu, isr);
            if (isr) Rw[wcnt + __popc(bal & lt)] = i;
            wcnt += __popc(bal);
        }
        runcnt = wcnt;
    }
    __syncthreads();   // L[] complete before edge pass reads neighbors

    // ---- pass 3: deduped vertical edges into PER-WARP segments ----
    {
        int* Ew = E + (w << 10);
        int wcnt = 0;
        const unsigned lt = (1u << lane) - 1u;
        #pragma unroll
        for (int ii = 0; ii < 16; ii++){
            int i = W + ii * 1024 + tid;
            bool okp = (i < HW) && SET(i);
            int e0 = -1, e1 = -1;
            if (okp){
                int c = i & (W - 1);
                bool lft = (c > 0) && SET(i-1);
                if (SET(i-W)){
                    if (!(lft && SET(i-W-1))) e0 = (L[i] << 14) | L[i-W];
                } else {
                    if (c > 0     && SET(i-W-1) && !lft)      e0 = (L[i] << 14) | L[i-W-1];
                    if (c < W-1   && SET(i-W+1) && !SET(i+1)) e1 = (L[i] << 14) | L[i-W+1];
                }
            }
            unsigned b0 = __ballot_sync(0xffffffffu, e0 >= 0);
            unsigned b1 = __ballot_sync(0xffffffffu, e1 >= 0);
            if (e0 >= 0) Ew[wcnt + __popc(b0 & lt)] = e0;
            int base1 = wcnt + __popc(b0);
            if (e1 >= 0) Ew[base1 + __popc(b1 & lt)] = e1;
            wcnt = base1 + __popc(b1);
        }
        if (lane == 0) s_wcnt[w] = runcnt | (wcnt << 16);
    }
    __syncthreads();
    const int my_e = s_wcnt[w] >> 16;     // this warp's edge count (uniform in warp)

    // ---- SV rounds: each warp hooks ITS edges; halving flatten over runs ----
    for (int round = 0; round < 64; round++){
        if (tid == 0) s_flag = 0;
        __syncthreads();
        bool any = false;
        int* Ew = E + (w << 10);
        for (int e = lane; e < my_e; e += 32){
            int pk = Ew[e];
            int a = pk >> 14, b2 = pk & 16383;
            int ra = L[a], rb = L[b2];
            int npk = (ra << 14) | rb;
            if (npk != pk) Ew[e] = npk;   // relabel toward roots
            bool ok = (ra != rb);
            unsigned act = __activemask();
            unsigned bal = __ballot_sync(act, ok);
            if (ok){
                int hi = ra > rb ? ra : rb;
                int lo = ra > rb ? rb : ra;
                unsigned grp = __match_any_sync(bal, hi) & bal;
                unsigned m   = __reduce_min_sync(grp, (unsigned)lo);
                if (lane == __ffs(grp) - 1) atomicMin(&L[hi], (int)m);
                any = true;
            }
        }
        if (any) s_flag = 1;
        __syncthreads();
        if (!s_flag) break;
        {   // path-halving flatten over run segments: benign races, monotone
            volatile int* Lv = (volatile int*)L;
            for (int t = tid; t < MAXRUN; t += 1024){
                if ((t & 255) < (s_wcnt[t >> 8] & 0xffff)){
                    int r = R[t];
                    int x = r, p = Lv[x];
                    for (;;){
                        int g = Lv[p];
                        if (g == p) break;
                        Lv[x] = g;
                        x = p; p = g;
                    }
                    if (Lv[r] != p) Lv[r] = p;
                }
            }
        }
        __syncthreads();
    }

    // ---- zero stats at run slots (edges dead now) ----
    for (int t = tid; t < MAXRUN; t += 1024){
        if ((t & 255) < (s_wcnt[t >> 8] & 0xffff)) s_acc[R[t]] = 0ull;
    }
    __syncthreads();

    // ---- FUSED propagate + stats: root per pixel written back; exact
    //      fixed-point REDUX; one fused 64-bit atomic per group leader. ----
    for (int i = tid; i < HW; i += 1024){
        int p = L[i];
        int root = (p >= 0) ? L[p] : -1;   // run slots hold roots; write-back is value-stable
        L[i] = root;
        unsigned grp = __match_any_sync(0xffffffffu, root);
        if (root >= 0){
            unsigned fx = __float2uint_rn(__ldg(&pb[i]) * 16777216.0f);  // exact: p = k*2^-24
            unsigned s  = __reduce_add_sync(grp, fx);
            if (lane == (__ffs(grp) - 1))
                atomicAdd(&s_acc[root],
                          ((unsigned long long)__popc(grp) << 40) | (unsigned long long)s);
        }
    }
    __syncthreads();

    // ---- top-3 by mean confidence + K (scan run segments) ----
    unsigned long long k0 = 0, k1 = 0, k2 = 0;
    int localK = 0;
    for (int t = tid; t < MAXRUN; t += 1024){
        if ((t & 255) < (s_wcnt[t >> 8] & 0xffff)){
            int r = R[t];
            unsigned long long v = s_acc[r];
            if (v != 0ull){                          // r is a root with pixels
                localK++;
                unsigned cnt = (unsigned)(v >> 40);
                unsigned long long sum = v & ((1ull << 40) - 1ull);
                float mean = (float)((double)sum / ((double)cnt * 16777216.0));
                unsigned long long key =
                    ((unsigned long long)__float_as_uint(mean) << 32) | (unsigned)(HW - 1 - r);
                ins3(k0, k1, k2, key);
            }
        }
    }
    localK = __reduce_add_sync(0xffffffffu, localK);     // one atomic per warp
    if (lane == 0) atomicAdd(&sK, localK);
    #pragma unroll
    for (int off = 16; off; off >>= 1){
        unsigned long long o0 = __shfl_down_sync(0xffffffffu, k0, off);
        unsigned long long o1 = __shfl_down_sync(0xffffffffu, k1, off);
        unsigned long long o2 = __shfl_down_sync(0xffffffffu, k2, off);
        ins3(k0, k1, k2, o0); ins3(k0, k1, k2, o1); ins3(k0, k1, k2, o2);
    }
    if (lane == 0){ s_r0[w] = k0; s_r1[w] = k1; s_r2[w] = k2; }
    __syncthreads();
    if (tid < 32){
        k0 = s_r0[tid]; k1 = s_r1[tid]; k2 = s_r2[tid];
        #pragma unroll
        for (int off = 16; off; off >>= 1){
            unsigned long long o0 = __shfl_down_sync(0xffffffffu, k0, off);
            unsigned long long o1 = __shfl_down_sync(0xffffffffu, k1, off);
            unsigned long long o2 = __shfl_down_sync(0xffffffffu, k2, off);
            ins3(k0, k1, k2, o0); ins3(k0, k1, k2, o1); ins3(k0, k1, k2, o2);
        }
        if (tid == 0){
            int K  = sK;
            int s0 = (HW - 1) - (int)(unsigned)(k0 & 0xffffffffull);
            int s1 = (HW - 1) - (int)(unsigned)(k1 & 0xffffffffull);
            int s2 = (HW - 1) - (int)(unsigned)(k2 & 0xffffffffull);
            int a0, a1, a2;
            if (K >= 3)      { a0 = s0; a1 = s1; a2 = s2; }
            else if (K == 2) { a0 = s0; a1 = s0; a2 = s1; }
            else             { a0 = s0; a1 = s0; a2 = s0; }
            s_slots[0] = a0; s_slots[1] = a1; s_slots[2] = a2;
            #pragma unroll
            for (int j = 0; j < 3; j++){
                s_box[j][0] = 0x7fffffff; s_box[j][1] = -1;
                s_box[j][2] = 0x7fffffff; s_box[j][3] = -1;
            }
        }
    }
    __syncthreads();

    // ---- bbox scan for the <=3 selected components (L[i] holds roots) ----
    if (sK > 0){
        for (int i = tid; i < HW; i += 1024){
            int root = L[i];
            int r = i >> 7, c = i & (W - 1);
            #pragma unroll
            for (int j = 0; j < 3; j++){
                bool mt = (root >= 0) && (root == s_slots[j]);
                unsigned bal = __ballot_sync(0xffffffffu, mt);
                if (mt){
                    unsigned mnr = __reduce_min_sync(bal, (unsigned)r);
                    unsigned mxr = __reduce_max_sync(bal, (unsigned)r);
                    unsigned mnc = __reduce_min_sync(bal, (unsigned)c);
                    unsigned mxc = __reduce_max_sync(bal, (unsigned)c);
                    if (lane == (__ffs(bal) - 1)){
                        atomicMin(&s_box[j][0], (int)mnr);
                        atomicMax(&s_box[j][1], (int)mxr);
                        atomicMin(&s_box[j][2], (int)mnc);
                        atomicMax(&s_box[j][3], (int)mxc);
                    }
                }
            }
        }
    }
    __syncthreads();

    // ---- emit nearest-interp index maps (src = a + floor(dst*(b-a)/out)) ----
    if (tid < 384){
        int j = tid >> 7, q = tid & 127;
        int mr, Mr, mc, Mc;
        if (sK == 0){ mr = 0; Mr = H; mc = 0; Mc = W; }
        else {
            mr = s_box[j][0]; Mr = s_box[j][1] + 1;
            mc = s_box[j][2]; Mc = s_box[j][3] + 1;
        }
        int v;
        if (q < 64) v = mr + ((q * (Mr - mr)) >> 6);
        else        { int x = q - 64; v = mc + ((x * (Mc - mc)) >> 6); }
        g_maps[b][j][q] = v;
    }
}

// Empirically-fastest gather: one block per (b, slot, c) plane.
__global__ void __launch_bounds__(256) gather_kernel(const float* __restrict__ feat,
                                                     float* __restrict__ out){
    __shared__ int sm[128];
    int bid  = blockIdx.x;
    int c    = bid % CF;
    int rem  = bid / CF;
    int slot = rem % 3;
    int b    = rem / 3;

    if (threadIdx.x < 128) sm[threadIdx.x] = g_maps[b][slot][threadIdx.x];
    __syncthreads();
    const int* rmap = sm;
    const int* cmap = sm + 64;

    const float* src = feat + ((size_t)(b * CF + c)) * HW;
    float4* dst = (float4*)(out + ((size_t)b * (3 * CF) + (size_t)slot * CF + c) * (H2 * W2));

    #pragma unroll
    for (int i = threadIdx.x; i < (H2 * W2) / 4; i += 256){
        int y  = i >> 4;
        int x4 = (i & 15) << 2;
        const float* row = src + rmap[y] * W;
        float4 v;
        v.x = __ldg(&row[cmap[x4 + 0]]);
        v.y = __ldg(&row[cmap[x4 + 1]]);
        v.z = __ldg(&row[cmap[x4 + 2]]);
        v.w = __ldg(&row[cmap[x4 + 3]]);
        __stcs(&dst[i], v);
    }
}

extern "C" void kernel_launch(void* const* d_in, const int* in_sizes, int n_in,
                              void* d_out, int out_size){
    const float* prob = (const float*)d_in[0];
    const float* feat = (const float*)d_in[1];
    if (in_sizes[0] != BATCH * HW){
        const float* t = prob; prob = feat; feat = t;
    }
    const int ccl_smem = (3 * HW + MAXRUN) * 4;            // 224KB dynamic (+ ~3KB static < 227KB cap)
    cudaFuncSetAttribute(ccl_kernel, cudaFuncAttributeMaxDynamicSharedMemorySize, ccl_smem);

    ccl_kernel<<<BATCH, 1024, ccl_smem>>>(prob);
    gather_kernel<<<BATCH * 3 * CF, 256>>>(feat, (float*)d_out);
}